// round 14
// baseline (speedup 1.0000x reference)
#include <cuda_runtime.h>
#include <cuda_fp16.h>
#include <cstdint>

// ---------------- problem constants ----------------
#define BSZ   256
#define CSZ   2048
#define NC    10000
#define LOGITS (256*10000)
#define FEAT_OFF (2*LOGITS)
#define NW_OFF   (2*LOGITS + BSZ*CSZ)

// ---------------- GEMM tiling (fp16) ----------------
#define BM 64
#define BN 96
#define BK 64
#define NT (CSZ / BK)              // 32 chunks
#define STAGES 3
#define STAGE_B ((BM + BN) * 128)  // 20480
#define B_OFF (BM * 128)
#define SMEM_TOTAL (STAGES * STAGE_B)   // 61440
#define NTHREADS 160               // 4 gemm warps (2m x 2n, 32x48) + 1 producer warp
#define NCTAS 420                  // 105 x 4, all co-resident at 3 CTAs/SM

__device__ __half g_W16[(size_t)NC * CSZ];
__device__ __half g_A16[(size_t)BSZ * CSZ];
__device__ int    g_cnt[NT];       // per-chunk ready counters (target NCTAS)

static __device__ __forceinline__ uint32_t swz(uint32_t off) {
    return off ^ ((off >> 3) & 0x70);
}
static __device__ __forceinline__ uint32_t smem_u32(const void* p) {
    uint32_t a;
    asm("{ .reg .u64 t; cvta.to.shared.u64 t, %1; cvt.u32.u64 %0, t; }" : "=r"(a) : "l"(p));
    return a;
}
static __device__ __forceinline__ void cp16(uint32_t dst, const void* src, uint32_t sz) {
    asm volatile("cp.async.cg.shared.global.L2::128B [%0], [%1], 16, %2;"
                 :: "r"(dst), "l"(src), "r"(sz) : "memory");
}
static __device__ __forceinline__ void ldsm4(uint32_t* r, uint32_t addr) {
    asm volatile("ldmatrix.sync.aligned.m8n8.x4.shared.b16 {%0,%1,%2,%3}, [%4];"
                 : "=r"(r[0]), "=r"(r[1]), "=r"(r[2]), "=r"(r[3]) : "r"(addr));
}
static __device__ __forceinline__ void mma_f16(float* c, const uint32_t* a, const uint32_t* b) {
    asm volatile(
        "mma.sync.aligned.m16n8k16.row.col.f32.f16.f16.f32 "
        "{%0,%1,%2,%3}, {%4,%5,%6,%7}, {%8,%9}, {%0,%1,%2,%3};"
        : "+f"(c[0]), "+f"(c[1]), "+f"(c[2]), "+f"(c[3])
        : "r"(a[0]), "r"(a[1]), "r"(a[2]), "r"(a[3]), "r"(b[0]), "r"(b[1]));
}
static __device__ __forceinline__ uint32_t h2bits(__half2 h) {
    return *reinterpret_cast<uint32_t*>(&h);
}
// consumer-warps-only barrier (producer warp never joins)
#define BAR_C() asm volatile("bar.sync 1, 128;" ::: "memory")

// ---------------------------------------------------------------------------
// Kernel 0: zero the chunk counters (stream-ordered before the fused kernel).
// ---------------------------------------------------------------------------
__global__ void init_kernel() {
    if (threadIdx.x < NT) g_cnt[threadIdx.x] = 0;
}

// ---------------------------------------------------------------------------
// Kernel 1 (fused): producer warp streams pool+wconv per K-chunk, consumer
// warps run the GEMM gated on per-chunk counters.
// ---------------------------------------------------------------------------
__global__ __launch_bounds__(NTHREADS, 3)
void fused_kernel(const float* __restrict__ f, const float* __restrict__ W,
                  float* __restrict__ out)
{
    extern __shared__ char smem[];
    const uint32_t sb = smem_u32(smem);

    const int tid  = threadIdx.x;
    const int wid  = tid >> 5, lane = tid & 31;
    const int cta  = blockIdx.y * gridDim.x + blockIdx.x;   // 0..419
    const int m0   = blockIdx.y * BM;
    const int n0   = blockIdx.x * BN;

    if (wid == 4) {
        // =================== PRODUCER WARP ===================
        const int gl = cta * 32 + lane;                      // 0..13439
        float* feat = out + FEAT_OFF;
        float* nw   = out + NW_OFF;
        if (cta == 0)
            for (int i = lane; i < BSZ; i += 32) nw[i] = 1.0f;

        const float4* Wf4 = reinterpret_cast<const float4*>(W);
        uint2* W16u = reinterpret_cast<uint2*>(g_W16);

        for (int t = 0; t < NT; t++) {
            // pool channels [64t, 64t+64) for all batches: 16384 (b,c) rows
            for (int p = gl; p < BSZ * 64; p += NCTAS * 32) {
                int b = p >> 6, cc = p & 63;
                int c = t * 64 + cc;
                const float4* src = reinterpret_cast<const float4*>(f)
                                    + ((size_t)b * CSZ + c) * 32;
                float sx = 0.f, sy = 0.f, sz = 0.f, sw = 0.f;
                #pragma unroll
                for (int i = 0; i < 32; i++) {
                    float4 v = src[i];
                    sx += v.x; sy += v.y; sz += v.z; sw += v.w;
                }
                float m = ((sx + sy) + (sz + sw)) * (1.0f / 128.0f);
                feat[(size_t)b * CSZ + c] = m;
                g_A16[(size_t)b * CSZ + c] = __float2half_rn(m);
            }
            // convert W columns [64t, 64t+64): 10000 rows x 16 float4 segs
            for (int idx = gl; idx < NC * 16; idx += NCTAS * 32) {
                int row = idx >> 4, seg = idx & 15;
                size_t o = (size_t)row * 512 + t * 16 + seg;
                float4 v = Wf4[o];
                W16u[o] = make_uint2(h2bits(__floats2half2_rn(v.x, v.y)),
                                     h2bits(__floats2half2_rn(v.z, v.w)));
            }
            __threadfence();
            __syncwarp();
            if (lane == 0) atomicAdd(&g_cnt[t], 1);
        }
        return;
    }

    // =================== CONSUMER WARPS (4): round-12 GEMM ===================
    const int wm = wid & 1;            // 2 warp rows x 32 m
    const int wn = wid >> 1;           // 2 warp cols x 48 n
    const int gr = lane >> 2;
    const int gc = lane & 3;

    float acc[2][6][4];
    #pragma unroll
    for (int i = 0; i < 2; i++)
        #pragma unroll
        for (int j = 0; j < 6; j++)
            #pragma unroll
            for (int q = 0; q < 4; q++) acc[i][j][q] = 0.0f;

    uint32_t aoff[2][4], boff[3][4];
    {
        int ar = (lane & 15);
        int as = (lane >> 4);
        int br = (lane & 7) + ((lane & 16) >> 1);
        int bs = (lane >> 3) & 1;
        #pragma unroll
        for (int s = 0; s < 4; s++) {
            #pragma unroll
            for (int mt = 0; mt < 2; mt++)
                aoff[mt][s] = swz((uint32_t)((wm * 32 + mt * 16 + ar) * 128 + (s * 2 + as) * 16));
            #pragma unroll
            for (int np = 0; np < 3; np++)
                boff[np][s] = swz((uint32_t)((wn * 48 + np * 16 + br) * 128 + (s * 2 + bs) * 16));
        }
    }

    auto load_chunk = [&](int t, int stg) {
        {   // gate on producer completion for chunk t (monotonic counter)
            volatile int* cp = g_cnt + t;
            while (*cp < NCTAS) __nanosleep(64);
        }
        const int k0 = t * BK;
        const uint32_t base = sb + stg * STAGE_B;
        #pragma unroll
        for (int j = 0; j < 4; j++) {              // A: 512 x 16B over 128 thr
            int idx = tid + 128 * j;
            int r = idx >> 3, c = idx & 7;
            cp16(base + swz(r * 128 + c * 16),
                 g_A16 + (size_t)(m0 + r) * CSZ + k0 + c * 8, 16);
        }
        #pragma unroll
        for (int j = 0; j < 6; j++) {              // B: 768 x 16B
            int idx = tid + 128 * j;
            int r = idx >> 3, c = idx & 7;
            int n = n0 + r;
            cp16(base + B_OFF + swz(r * 128 + c * 16),
                 g_W16 + (size_t)(n < NC ? n : 0) * CSZ + k0 + c * 8,
                 n < NC ? 16u : 0u);
        }
        asm volatile("cp.async.commit_group;" ::: "memory");
    };

    load_chunk(0, 0);
    load_chunk(1, 1);

    for (int t = 0; t < NT; t++) {
        const int stg = t % STAGES;
        if (t + 1 < NT) asm volatile("cp.async.wait_group 1;" ::: "memory");
        else            asm volatile("cp.async.wait_group 0;" ::: "memory");
        BAR_C();
        if (t + 2 < NT) load_chunk(t + 2, (t + 2) % STAGES);

        const uint32_t aBase = sb + stg * STAGE_B;
        const uint32_t bBase = aBase + B_OFF;

        #pragma unroll
        for (int s = 0; s < 4; s++) {
            uint32_t af[2][4], bf[3][4];
            ldsm4(af[0], aBase + aoff[0][s]);
            ldsm4(af[1], aBase + aoff[1][s]);
            ldsm4(bf[0], bBase + boff[0][s]);
            ldsm4(bf[1], bBase + boff[1][s]);
            ldsm4(bf[2], bBase + boff[2][s]);
            #pragma unroll
            for (int mt = 0; mt < 2; mt++)
                #pragma unroll
                for (int nt = 0; nt < 6; nt++)
                    mma_f16(acc[mt][nt], af[mt], &bf[nt >> 1][(nt & 1) * 2]);
        }
    }

    float* cls  = out;
    float* pred = out + LOGITS;
    #pragma unroll
    for (int mt = 0; mt < 2; mt++) {
        #pragma unroll
        for (int half = 0; half < 2; half++) {
            int m = m0 + wm * 32 + mt * 16 + gr + half * 8;
            long base = (long)m * NC;
            #pragma unroll
            for (int nt = 0; nt < 6; nt++) {
                int n = n0 + wn * 48 + nt * 8 + gc * 2;
                if (n < NC) {
                    float2 v = make_float2(acc[mt][nt][half * 2], acc[mt][nt][half * 2 + 1]);
                    *reinterpret_cast<float2*>(cls  + base + n) = v;
                    *reinterpret_cast<float2*>(pred + base + n) = v;
                }
            }
        }
    }
}

// ---------------------------------------------------------------------------
extern "C" void kernel_launch(void* const* d_in, const int* in_sizes, int n_in,
                              void* d_out, int out_size) {
    const float* features = (const float*)d_in[0];
    // d_in[1] = targets (unused: new_weight collapses to exactly 1.0)
    const float* weight   = (const float*)d_in[2];
    float* out = (float*)d_out;

    init_kernel<<<1, 32>>>();

    cudaFuncSetAttribute(fused_kernel, cudaFuncAttributeMaxDynamicSharedMemorySize, SMEM_TOTAL);
    dim3 grid((NC + BN - 1) / BN, BSZ / BM);   // 105 x 4 = 420 CTAs (all resident)
    fused_kernel<<<grid, NTHREADS, SMEM_TOTAL>>>(features, weight, out);
}